// round 9
// baseline (speedup 1.0000x reference)
#include <cuda_runtime.h>

#define IMG_W 512
#define IMG_H 512
#define PLANE (IMG_W * IMG_H)
#define RPT   8
#define STRIPS_PER_PLANE (IMG_H / RPT)   // 64
#define FULLMASK 0xffffffffu

__device__ __forceinline__ float med3f(float a, float b, float c) {
    return fmaxf(fminf(a, b), fminf(fmaxf(a, b), c));
}

struct RawRow {
    float4 v;        // aligned 4 columns
    float le, re;    // cross-warp halo (valid only on lanes 0 / 31)
};

struct SortedRow {
    float lo0, lo1, lo2, lo3;
    float mi0, mi1, mi2, mi3;
    float hi0, hi1, hi2, hi3;
};

// Prefetch stage: one coalesced LDG.128 + (lanes 0/31 only) one predicated
// scalar LDG for the cross-warp halo. No strided multi-line scalar loads.
__device__ __forceinline__ RawRow load_raw(const float* __restrict__ ip,
                                           int y, int x0, int lane,
                                           bool needL, bool needR) {
    const float* __restrict__ rp = ip + y * IMG_W;
    RawRow o;
    o.v = *(const float4*)(rp + x0);
    o.le = 0.0f; o.re = 0.0f;
    if (lane == 0  && needL) o.le = rp[x0 - 1];
    if (lane == 31 && needR) o.re = rp[x0 + 4];
    return o;
}

// Consume stage: halos from neighbor lanes' registers (shfl), edges from own regs.
__device__ __forceinline__ SortedRow sort_row(const RawRow& rr, int lane,
                                              bool edgeL, bool edgeR) {
    float l = __shfl_up_sync(FULLMASK, rr.v.w, 1);
    float r = __shfl_down_sync(FULLMASK, rr.v.x, 1);
    if (lane == 0)  l = edgeL ? rr.v.y : rr.le;   // reflect(x=-1) = col 1 = v.y
    if (lane == 31) r = edgeR ? rr.v.z : rr.re;   // reflect(x=512) = col 510 = v.z

    float s0 = l, s1 = rr.v.x, s2 = rr.v.y, s3 = rr.v.z, s4 = rr.v.w, s5 = r;

    SortedRow o;
    #define SORT3(a_, b_, c_, LO, MI, HI) {            \
        float a = (a_), b = (b_), c = (c_), t;          \
        t = fminf(a, b); b = fmaxf(a, b); a = t;        \
        t = fminf(b, c); c = fmaxf(b, c); b = t;        \
        t = fminf(a, b); b = fmaxf(a, b); a = t;        \
        o.LO = a; o.MI = b; o.HI = c; }
    SORT3(s0, s1, s2, lo0, mi0, hi0);
    SORT3(s1, s2, s3, lo1, mi1, hi1);
    SORT3(s2, s3, s4, lo2, mi2, hi2);
    SORT3(s3, s4, s5, lo3, mi3, hi3);
    #undef SORT3
    return o;
}

__device__ __forceinline__ float tail(float lA, float lB, float lC,
                                      float mA, float mB, float mC,
                                      float hA, float hB, float hC) {
    float mx = fmaxf(fmaxf(lA, lB), lC);   // max of mins
    float mn = fminf(fminf(hA, hB), hC);   // min of maxes
    float md = med3f(mA, mB, mC);          // med of mids
    return med3f(mx, md, mn);
}

__global__ __launch_bounds__(256)
void MedianFilter2D_68745246540291_kernel(const float* __restrict__ in,
                                          float* __restrict__ out) {
    const int tid   = threadIdx.x;
    const int lane  = tid & 31;
    const int t128  = tid & 127;
    const int strip = blockIdx.x * 2 + (tid >> 7);

    const int plane = strip >> 6;                 // / STRIPS_PER_PLANE
    const int sy    = strip & (STRIPS_PER_PLANE - 1);
    const int y0    = sy * RPT;
    const int x0    = t128 * 4;

    const float* __restrict__ ip = in  + (size_t)plane * PLANE;
    float*       __restrict__ op = out + (size_t)plane * PLANE;

    const bool edgeL = (x0 == 0);             // this lane-0 is at image edge
    const bool edgeR = (x0 + 4 >= IMG_W);     // this lane-31 is at image edge
    const bool needL = (lane == 0)  && !edgeL;
    const bool needR = (lane == 31) && !edgeR;

    const int ytop = (sy == 0)                    ? 1         : y0 - 1;
    const int ybot = (sy == STRIPS_PER_PLANE - 1) ? IMG_H - 2 : y0 + RPT;

    SortedRow A = sort_row(load_raw(ip, ytop, x0, lane, needL, needR), lane, edgeL, edgeR);
    SortedRow B = sort_row(load_raw(ip, y0,   x0, lane, needL, needR), lane, edgeL, edgeR);
    RawRow nxt  = load_raw(ip, y0 + 1, x0, lane, needL, needR);

    #pragma unroll
    for (int i = 0; i < RPT; i++) {
        RawRow cur = nxt;
        if (i + 1 < RPT) {
            const int yn = (i + 2 == RPT) ? ybot : (y0 + i + 2);
            nxt = load_raw(ip, yn, x0, lane, needL, needR);
        }

        SortedRow C = sort_row(cur, lane, edgeL, edgeR);

        float4 res;
        res.x = tail(A.lo0, B.lo0, C.lo0, A.mi0, B.mi0, C.mi0, A.hi0, B.hi0, C.hi0);
        res.y = tail(A.lo1, B.lo1, C.lo1, A.mi1, B.mi1, C.mi1, A.hi1, B.hi1, C.hi1);
        res.z = tail(A.lo2, B.lo2, C.lo2, A.mi2, B.mi2, C.mi2, A.hi2, B.hi2, C.hi2);
        res.w = tail(A.lo3, B.lo3, C.lo3, A.mi3, B.mi3, C.mi3, A.hi3, B.hi3, C.hi3);

        *(float4*)(op + (size_t)(y0 + i) * IMG_W + x0) = res;

        A = B; B = C;   // register renaming under full unroll
    }
}

extern "C" void kernel_launch(void* const* d_in, const int* in_sizes, int n_in,
                              void* d_out, int out_size) {
    const float* image = (const float*)d_in[0];
    float* out = (float*)d_out;

    // 48 planes * 64 strips(8 rows); 2 strips per 256-thread block -> 1536 blocks
    dim3 block(256, 1, 1);
    dim3 grid(48 * STRIPS_PER_PLANE / 2, 1, 1);
    MedianFilter2D_68745246540291_kernel<<<grid, block>>>(image, out);
}

// round 11
// speedup vs baseline: 1.0847x; 1.0847x over previous
#include <cuda_runtime.h>

#define IMG_W 512
#define IMG_H 512
#define PLANE (IMG_W * IMG_H)
#define RPT   8
#define STRIPS_PER_PLANE (IMG_H / RPT)   // 64

__device__ __forceinline__ float med3f(float a, float b, float c) {
    return fmaxf(fminf(a, b), fminf(fmaxf(a, b), c));
}

// Compare-exchange on the FMA pipe (FADD/FMUL only, no FMNMX):
//   min = 0.5*(a+b) - 0.5*|a-b|,  max = 0.5*(a+b) + 0.5*|a-b|
// Exact to ~1 ulp of |a|+|b| — far below the 1e-3 gate; inputs are finite.
__device__ __forceinline__ void ce_fma(float& a, float& b) {
    float d  = a - b;
    float s  = a + b;
    float h  = 0.5f * fabsf(d);
    float hs = 0.5f * s;
    a = hs - h;   // ~min
    b = hs + h;   // ~max
}

// Compare-exchange on the ALU pipe (FMNMX)
__device__ __forceinline__ void ce_alu(float& a, float& b) {
    float t = fminf(a, b);
    b = fmaxf(a, b);
    a = t;
}

struct RawRow {
    float4 v;
    float l, r;
};

struct SortedRow {
    float lo0, lo1, lo2, lo3;
    float mi0, mi1, mi2, mi3;
    float hi0, hi1, hi2, hi3;
};

__device__ __forceinline__ RawRow load_raw(const float* __restrict__ ip,
                                           int y, int x0, int xl, int xr) {
    const float* __restrict__ rp = ip + y * IMG_W;
    RawRow o;
    o.v = *(const float4*)(rp + x0);
    o.l = rp[xl];
    o.r = rp[xr];
    return o;
}

// Horizontal 3-sorts: columns 0..2 on the FMA pipe, column 3 on the ALU pipe.
// Per row: 9 CEs -> fma (54 ops), 3 CEs -> alu (6 ops). Tail stays on alu.
__device__ __forceinline__ SortedRow sort_row(const RawRow& rr) {
    float s0 = rr.l, s1 = rr.v.x, s2 = rr.v.y, s3 = rr.v.z, s4 = rr.v.w, s5 = rr.r;
    SortedRow o;
    #define SORT3F(a_, b_, c_, LO, MI, HI) {            \
        float a = (a_), b = (b_), c = (c_);              \
        ce_fma(a, b); ce_fma(b, c); ce_fma(a, b);        \
        o.LO = a; o.MI = b; o.HI = c; }
    #define SORT3A(a_, b_, c_, LO, MI, HI) {            \
        float a = (a_), b = (b_), c = (c_);              \
        ce_alu(a, b); ce_alu(b, c); ce_alu(a, b);        \
        o.LO = a; o.MI = b; o.HI = c; }
    SORT3F(s0, s1, s2, lo0, mi0, hi0);
    SORT3F(s1, s2, s3, lo1, mi1, hi1);
    SORT3F(s2, s3, s4, lo2, mi2, hi2);
    SORT3A(s3, s4, s5, lo3, mi3, hi3);
    #undef SORT3F
    #undef SORT3A
    return o;
}

__device__ __forceinline__ float tail(float lA, float lB, float lC,
                                      float mA, float mB, float mC,
                                      float hA, float hB, float hC) {
    float mx = fmaxf(fmaxf(lA, lB), lC);   // max of mins
    float mn = fminf(fminf(hA, hB), hC);   // min of maxes
    float md = med3f(mA, mB, mC);          // med of mids
    return med3f(mx, md, mn);
}

__global__ __launch_bounds__(256)
void MedianFilter2D_68745246540291_kernel(const float* __restrict__ in,
                                          float* __restrict__ out) {
    const int tid   = threadIdx.x;
    const int t128  = tid & 127;
    const int strip = blockIdx.x * 2 + (tid >> 7);

    const int plane = strip >> 6;                 // / STRIPS_PER_PLANE
    const int sy    = strip & (STRIPS_PER_PLANE - 1);
    const int y0    = sy * RPT;
    const int x0    = t128 * 4;

    const float* __restrict__ ip = in  + (size_t)plane * PLANE;
    float*       __restrict__ op = out + (size_t)plane * PLANE;

    const int xl = (t128 == 0)   ? 1         : x0 - 1;
    const int xr = (t128 == 127) ? IMG_W - 2 : x0 + 4;

    const int ytop = (sy == 0)                    ? 1         : y0 - 1;
    const int ybot = (sy == STRIPS_PER_PLANE - 1) ? IMG_H - 2 : y0 + RPT;

    SortedRow A = sort_row(load_raw(ip, ytop, x0, xl, xr));
    SortedRow B = sort_row(load_raw(ip, y0,   x0, xl, xr));
    RawRow nxt  = load_raw(ip, y0 + 1, x0, xl, xr);

    #pragma unroll
    for (int i = 0; i < RPT; i++) {
        RawRow cur = nxt;
        if (i + 1 < RPT) {
            const int yn = (i + 2 == RPT) ? ybot : (y0 + i + 2);
            nxt = load_raw(ip, yn, x0, xl, xr);
        }

        SortedRow C = sort_row(cur);

        float4 res;
        res.x = tail(A.lo0, B.lo0, C.lo0, A.mi0, B.mi0, C.mi0, A.hi0, B.hi0, C.hi0);
        res.y = tail(A.lo1, B.lo1, C.lo1, A.mi1, B.mi1, C.mi1, A.hi1, B.hi1, C.hi1);
        res.z = tail(A.lo2, B.lo2, C.lo2, A.mi2, B.mi2, C.mi2, A.hi2, B.hi2, C.hi2);
        res.w = tail(A.lo3, B.lo3, C.lo3, A.mi3, B.mi3, C.mi3, A.hi3, B.hi3, C.hi3);

        *(float4*)(op + (size_t)(y0 + i) * IMG_W + x0) = res;

        A = B; B = C;   // register renaming under full unroll
    }
}

extern "C" void kernel_launch(void* const* d_in, const int* in_sizes, int n_in,
                              void* d_out, int out_size) {
    const float* image = (const float*)d_in[0];
    float* out = (float*)d_out;

    // 48 planes * 64 strips(8 rows); 2 strips per 256-thread block -> 1536 blocks
    dim3 block(256, 1, 1);
    dim3 grid(48 * STRIPS_PER_PLANE / 2, 1, 1);
    MedianFilter2D_68745246540291_kernel<<<grid, block>>>(image, out);
}